// round 9
// baseline (speedup 1.0000x reference)
#include <cuda_runtime.h>
#include <cuda_fp16.h>
#include <cstdint>
#include <math.h>

#define BB 8
#define CC 64
#define HH 128
#define WW 128
#define HWD 16384
#define NS 3
#define K54 54
#define WSP 56                      // padded weight pitch (floats) per tap
#define CNT 131072.0f
#define BN_EPS 1e-5f

// ---------------- scratch (device globals; no runtime allocation) ----------
__device__ __half g_z[NS * BB * HWD * CC];     // z = Wc·x, [s][b][hw][o] fp16 (50 MB)
__device__ float g_off[BB * HWD * K54];        // offsets channel-last (28.3 MB)
__device__ float g_Wt[CC * 9 * WSP];           // Wp as [ci][tap][k54 padded to 56]
__device__ float g_y[NS * BB * CC * HWD];      // pre-BN y [s][b][o][hw] (100 MB)
__device__ float g_sum[NS * CC];
__device__ float g_sumsq[NS * CC];
__device__ float g_AB[NS * CC * 2];            // A = gamma*rsqrt(var+eps), B = beta-mu*A

// ---------------- cp.async helpers -----------------------------------------
__device__ __forceinline__ void cpa4(unsigned s, const void* g, bool v) {
    asm volatile("cp.async.ca.shared.global [%0], [%1], 4, %2;"
                 :: "r"(s), "l"(g), "r"(v ? 4u : 0u));
}
__device__ __forceinline__ void cpa16(unsigned s, const void* g) {
    asm volatile("cp.async.cg.shared.global [%0], [%1], 16;" :: "r"(s), "l"(g));
}
__device__ __forceinline__ void cpa_commit() {
    asm volatile("cp.async.commit_group;");
}
template <int N>
__device__ __forceinline__ void cpa_wait() {
    asm volatile("cp.async.wait_group %0;" :: "n"(N));
}

// ---------------- k1: transpose Wp (padded) + zero stats --------------------
__global__ void k_prep(const float* __restrict__ Wp) {
    int idx = blockIdx.x * blockDim.x + threadIdx.x;
    if (idx < CC * 9 * WSP) {
        int ci = idx / (9 * WSP);
        int rem = idx % (9 * WSP);
        int tap = rem / WSP;
        int k = rem % WSP;
        g_Wt[idx] = (k < K54) ? Wp[(k * CC + ci) * 9 + tap] : 0.f;
    }
    if (idx < NS * CC) { g_sum[idx] = 0.f; g_sumsq[idx] = 0.f; }
}

// ---------------- k_mix: z[s][b][hw][o] = sum_c Wc[s][o][c] * x[b][c][hw] ---
// block = 256 thr, 64 pixels; thread = (pixel, 16 outputs). fp32 math, fp16 out.
__global__ void __launch_bounds__(256) k_mix(const float* __restrict__ x,
                                             const float* __restrict__ WcG) {
    __shared__ float xs[64 * 65];     // [c][p] pitch 65
    __shared__ float wc[64 * 64];     // [c][o]
    int hw0 = blockIdx.x * 64;
    int b = blockIdx.y, s = blockIdx.z;
    int tid = threadIdx.x;

    for (int idx = tid; idx < 4096; idx += 256) {
        int o = idx >> 6, c = idx & 63;
        wc[c * 64 + o] = WcG[s * 4096 + idx];          // Wc[o][c] -> [c][o]
    }
    for (int idx = tid; idx < 4096; idx += 256) {
        int c = idx >> 6, p = idx & 63;
        xs[c * 65 + p] = x[((size_t)b * CC + c) * HWD + hw0 + p];
    }
    __syncthreads();

    int p = tid & 63;
    int ob = (tid >> 6) * 16;
    float acc[16];
#pragma unroll
    for (int q = 0; q < 16; q++) acc[q] = 0.f;
    for (int c = 0; c < 64; c++) {
        float xv = xs[c * 65 + p];
        const float4* w4 = (const float4*)&wc[c * 64 + ob];
#pragma unroll
        for (int j = 0; j < 4; j++) {
            float4 wv = w4[j];
            acc[4 * j + 0] = fmaf(xv, wv.x, acc[4 * j + 0]);
            acc[4 * j + 1] = fmaf(xv, wv.y, acc[4 * j + 1]);
            acc[4 * j + 2] = fmaf(xv, wv.z, acc[4 * j + 2]);
            acc[4 * j + 3] = fmaf(xv, wv.w, acc[4 * j + 3]);
        }
    }
    // pack 16 fp32 -> 16 fp16 (32B) and store
    __half2 hz[8];
#pragma unroll
    for (int j = 0; j < 8; j++) hz[j] = __floats2half2_rn(acc[2 * j], acc[2 * j + 1]);
    __half* dst = g_z + (((size_t)(s * BB + b)) * HWD + hw0 + p) * CC + ob;
    ((uint4*)dst)[0] = ((uint4*)hz)[0];
    ((uint4*)dst)[1] = ((uint4*)hz)[1];
}

// ---------------- k2: 3x3 offset conv, cp.async double-buffered -------------
__global__ void __launch_bounds__(128) k_conv(const float* __restrict__ x,
                                              const float* __restrict__ bp) {
    __shared__ float xs[2][3 * 132];   // rows h-1..h+1, padded cols
    __shared__ float ws[2][9 * WSP];   // [tap][k54] pitch 56
    int b = blockIdx.y;
    int h = blockIdx.x;
    int w = threadIdx.x;

    unsigned xs_s[2], ws_s[2];
    xs_s[0] = (unsigned)__cvta_generic_to_shared(&xs[0][0]);
    xs_s[1] = (unsigned)__cvta_generic_to_shared(&xs[1][0]);
    ws_s[0] = (unsigned)__cvta_generic_to_shared(&ws[0][0]);
    ws_s[1] = (unsigned)__cvta_generic_to_shared(&ws[1][0]);

    const float* xb = x + (size_t)b * CC * HWD;

    auto prefetch = [&](int ci, int bi) {
        const float* xc = xb + (size_t)ci * HWD;
#pragma unroll
        for (int it = 0; it < 4; it++) {
            int idx = w + it * 128;
            if (idx < 396) {
                int r = idx / 132, cw = idx % 132 - 1;
                int hh = h - 1 + r;
                bool valid = (hh >= 0) & (hh < HH) & (cw >= 0) & (cw < WW);
                const float* gp = xc + min(max(hh, 0), HH - 1) * WW + min(max(cw, 0), WW - 1);
                cpa4(xs_s[bi] + idx * 4, gp, valid);
            }
        }
        if (w < 126)
            cpa16(ws_s[bi] + w * 16, &g_Wt[ci * 9 * WSP + w * 4]);
    };

    float acc[K54];
#pragma unroll
    for (int k = 0; k < K54; k++) acc[k] = 0.f;

    prefetch(0, 0);
    cpa_commit();

    for (int ci = 0; ci < CC; ci++) {
        int bi = ci & 1;
        __syncthreads();
        if (ci + 1 < CC) {
            prefetch(ci + 1, bi ^ 1);
            cpa_commit();
            cpa_wait<1>();
        } else {
            cpa_wait<0>();
        }
        __syncthreads();

        float xv[9];
#pragma unroll
        for (int dh = 0; dh < 3; dh++)
#pragma unroll
            for (int dw = 0; dw < 3; dw++)
                xv[dh * 3 + dw] = xs[bi][dh * 132 + w + dw];
#pragma unroll
        for (int tap = 0; tap < 9; tap++) {
            float a = xv[tap];
            const float4* wr = (const float4*)&ws[bi][tap * WSP];
#pragma unroll
            for (int k4 = 0; k4 < 13; k4++) {
                float4 wv = wr[k4];
                int k = k4 * 4;
                acc[k + 0] = fmaf(a, wv.x, acc[k + 0]);
                acc[k + 1] = fmaf(a, wv.y, acc[k + 1]);
                acc[k + 2] = fmaf(a, wv.z, acc[k + 2]);
                acc[k + 3] = fmaf(a, wv.w, acc[k + 3]);
            }
            acc[52] = fmaf(a, ws[bi][tap * WSP + 52], acc[52]);
            acc[53] = fmaf(a, ws[bi][tap * WSP + 53], acc[53]);
        }
    }
    float* op = g_off + ((size_t)b * HWD + h * WW + w) * K54;
#pragma unroll
    for (int k = 0; k < K54; k++) {
        float sc = (k < 18) ? 1.f : ((k < 36) ? 2.f : 3.f);
        op[k] = (acc[k] + bp[k]) * sc;
    }
}

// ---------------- k_gather: gather+bilinear over z (= y directly) + stats ---
// block = 256 thr, 32 pixels of one (s,b,h) quarter-row; 8 lanes/pixel.
// No GEMM phase: gather(Wc·x) == Wc·gather(x) by linearity.
__global__ void __launch_bounds__(256, 3) k_gather() {
    __shared__ float off_sh[32 * 19];     // [p][18] pitch 19
    __shared__ float sh_y[32 * 65];       // [p][o] pitch 65

    int h = blockIdx.x >> 2;
    int w0 = (blockIdx.x & 3) * 32;
    int b = blockIdx.y, s = blockIdx.z;
    int tid = threadIdx.x;

    {
        const float* ob = g_off + ((size_t)(b * HWD + h * WW + w0)) * K54 + s * 18;
        for (int idx = tid; idx < 32 * 18; idx += 256) {
            int p = idx / 18, j = idx % 18;
            off_sh[p * 19 + j] = ob[p * K54 + j];
        }
    }
    __syncthreads();

    const __half* zb = g_z + ((size_t)(s * BB + b)) * HWD * CC;
    const float inv9 = 1.f / 9.f;
    {
        int p = tid >> 3;                  // 0..31
        int l = tid & 7;                   // channel octet
        const float* offp = &off_sh[p * 19];

        int raws[9]; float fxs[9], fys[9];
#pragma unroll
        for (int n = 0; n < 9; n++) {
            float px = (float)(h + n / 3) + offp[n];
            float py = (float)(w0 + p + n % 3) + offp[9 + n];
            float flx = floorf(px), fly = floorf(py);
            fxs[n] = px - flx; fys[n] = py - fly;
            raws[n] = (int)(flx * 128.f + fly);
        }

        float acc[8];
#pragma unroll
        for (int j = 0; j < 8; j++) acc[j] = 0.f;
#pragma unroll
        for (int n = 0; n < 9; n++) {
            int raw = raws[n];
            float fx = fxs[n], fy = fys[n];
            float wlt = (1.f - fx) * (1.f - fy);
            float wrb = fx * fy;
            float wlb = (1.f - fx) * fy;       // corner raw+1
            float wrt = fx * (1.f - fy);       // corner raw+128
            int i0 = min(max(raw, 0), HWD - 1);
            int i1 = min(max(raw + 1, 0), HWD - 1);
            int i2 = min(max(raw + 128, 0), HWD - 1);
            int i3 = min(max(raw + 129, 0), HWD - 1);
            uint4 v0 = *(const uint4*)(zb + (size_t)i0 * CC + l * 8);
            uint4 v1 = *(const uint4*)(zb + (size_t)i1 * CC + l * 8);
            uint4 v2 = *(const uint4*)(zb + (size_t)i2 * CC + l * 8);
            uint4 v3 = *(const uint4*)(zb + (size_t)i3 * CC + l * 8);
            const __half2* h0 = (const __half2*)&v0;
            const __half2* h1 = (const __half2*)&v1;
            const __half2* h2 = (const __half2*)&v2;
            const __half2* h3 = (const __half2*)&v3;
#pragma unroll
            for (int k = 0; k < 4; k++) {
                float2 f0 = __half22float2(h0[k]);
                float2 f1 = __half22float2(h1[k]);
                float2 f2 = __half22float2(h2[k]);
                float2 f3 = __half22float2(h3[k]);
                acc[2 * k + 0] = fmaf(wlt, f0.x, acc[2 * k + 0]);
                acc[2 * k + 1] = fmaf(wlt, f0.y, acc[2 * k + 1]);
                acc[2 * k + 0] = fmaf(wlb, f1.x, acc[2 * k + 0]);
                acc[2 * k + 1] = fmaf(wlb, f1.y, acc[2 * k + 1]);
                acc[2 * k + 0] = fmaf(wrt, f2.x, acc[2 * k + 0]);
                acc[2 * k + 1] = fmaf(wrt, f2.y, acc[2 * k + 1]);
                acc[2 * k + 0] = fmaf(wrb, f3.x, acc[2 * k + 0]);
                acc[2 * k + 1] = fmaf(wrb, f3.y, acc[2 * k + 1]);
            }
        }
#pragma unroll
        for (int j = 0; j < 8; j++) sh_y[p * 65 + l * 8 + j] = acc[j] * inv9;
    }
    __syncthreads();

    // epilogue: coalesced y write + BN partial stats (warp over 32 pixels)
    int p2 = tid & 31;
    int obase = (tid >> 5) * 8;
    float* yb = g_y + ((size_t)(s * BB + b) * CC) * HWD + h * WW + w0;
    int lane = tid & 31;
#pragma unroll
    for (int q = 0; q < 8; q++) {
        float v = sh_y[p2 * 65 + obase + q];
        yb[(size_t)(obase + q) * HWD + p2] = v;
        float v2 = v * v;
#pragma unroll
        for (int ofs = 16; ofs > 0; ofs >>= 1) {
            v += __shfl_down_sync(0xffffffffu, v, ofs);
            v2 += __shfl_down_sync(0xffffffffu, v2, ofs);
        }
        if (lane == 0) {
            atomicAdd(&g_sum[s * CC + obase + q], v);
            atomicAdd(&g_sumsq[s * CC + obase + q], v2);
        }
    }
}

// ---------------- k4: finalize BN coefficients ------------------------------
__global__ void k_stats(const float* __restrict__ gamma, const float* __restrict__ beta) {
    int t = threadIdx.x;
    if (t < NS * CC) {
        float inv = 1.f / CNT;
        float mu = g_sum[t] * inv;
        float var = g_sumsq[t] * inv - mu * mu;
        float A = gamma[t] * rsqrtf(var + BN_EPS);
        g_AB[t * 2] = A;
        g_AB[t * 2 + 1] = beta[t] - mu * A;
    }
}

// ---------------- k5: normalize + SiLU + average scales ---------------------
__global__ void k_final(float* __restrict__ out) {
    int idx = blockIdx.x * blockDim.x + threadIdx.x;   // over B*C*HWD
    int o = (idx >> 14) & 63;
    float r = 0.f;
#pragma unroll
    for (int s = 0; s < NS; s++) {
        float v = g_y[(size_t)s * BB * CC * HWD + idx];
        int t = s * CC + o;
        float yn = fmaf(v, g_AB[t * 2], g_AB[t * 2 + 1]);
        r += yn / (1.f + expf(-yn));
    }
    out[idx] = r * (1.f / 3.f);
}

// ---------------- launch ----------------------------------------------------
extern "C" void kernel_launch(void* const* d_in, const int* in_sizes, int n_in,
                              void* d_out, int out_size) {
    const float* x     = (const float*)d_in[0];
    const float* Wp    = (const float*)d_in[1];
    const float* bp    = (const float*)d_in[2];
    const float* Wc    = (const float*)d_in[3];
    const float* gamma = (const float*)d_in[4];
    const float* beta  = (const float*)d_in[5];
    float* out = (float*)d_out;

    k_prep<<<((CC * 9 * WSP) + 255) / 256, 256>>>(Wp);
    k_mix<<<dim3(HWD / 64, BB, NS), 256>>>(x, Wc);
    k_conv<<<dim3(HH, BB), 128>>>(x, bp);
    k_gather<<<dim3(HH * 4, BB, NS), 256>>>();
    k_stats<<<1, 256>>>(gamma, beta);
    k_final<<<(BB * CC * HWD) / 256, 256>>>(out);
}

// round 10
// speedup vs baseline: 1.1992x; 1.1992x over previous
#include <cuda_runtime.h>
#include <cuda_fp16.h>
#include <cstdint>
#include <math.h>

#define BB 8
#define CC 64
#define HH 128
#define WW 128
#define HWD 16384
#define NS 3
#define K54 54
#define WSP 56                      // padded weight pitch (floats) per tap
#define CNT 131072.0f
#define BN_EPS 1e-5f

// dyn smem layout for k_gather (bytes)
#define SM_WC_F    4096             // Wc [c][o]            (floats)
#define SM_XOFF_F  (32 * 65)        // xoff [p][c] pitch 65 (floats)
#define SM_OFF_F   (32 * 19)        // off  [p][18] pitch 19(floats)
#define SM_HDR_B   ((SM_WC_F + SM_XOFF_F + SM_OFF_F) * 4)   // 27136, 16B-aligned
#define SM_STAGE_B (4 * 32 * 4 * 128)                       // 4 slots x 32 px x 4 corners x 128B
#define SM_TOTAL_B (SM_HDR_B + SM_STAGE_B)                  // 92672

// ---------------- scratch (device globals; no runtime allocation) ----------
__device__ __half g_xH[BB * HWD * CC];         // x as [b][hw][c] fp16 (16.8 MB)
__device__ float g_off[BB * HWD * K54];        // offsets channel-last (28.3 MB)
__device__ float g_Wt[CC * 9 * WSP];           // Wp as [ci][tap][k54 padded to 56]
__device__ float g_y[NS * BB * CC * HWD];      // pre-BN y [s][b][o][hw] (100 MB)
__device__ float g_sum[NS * CC];
__device__ float g_sumsq[NS * CC];
__device__ float g_AB[NS * CC * 2];            // A = gamma*rsqrt(var+eps), B = beta-mu*A

// ---------------- cp.async helpers -----------------------------------------
__device__ __forceinline__ void cpa4(unsigned s, const void* g, bool v) {
    asm volatile("cp.async.ca.shared.global [%0], [%1], 4, %2;"
                 :: "r"(s), "l"(g), "r"(v ? 4u : 0u));
}
__device__ __forceinline__ void cpa16(unsigned s, const void* g) {
    asm volatile("cp.async.cg.shared.global [%0], [%1], 16;" :: "r"(s), "l"(g));
}
__device__ __forceinline__ void cpa16ca(unsigned s, const void* g) {
    asm volatile("cp.async.ca.shared.global [%0], [%1], 16;" :: "r"(s), "l"(g));
}
__device__ __forceinline__ void cpa_commit() {
    asm volatile("cp.async.commit_group;");
}
template <int N>
__device__ __forceinline__ void cpa_wait() {
    asm volatile("cp.async.wait_group %0;" :: "n"(N));
}

// ---------------- k0: transpose x (b,c,hw) -> (b,hw,c) fp16 ----------------
__global__ void k_transpose(const float* __restrict__ x) {
    __shared__ float t[32][33];                // t[c_local][hw_local]
    int b = blockIdx.z;
    int hw0 = blockIdx.x * 32;
    int c0 = blockIdx.y * 32;
    int tx = threadIdx.x, ty = threadIdx.y;   // (32, 8)
    int tid = ty * 32 + tx;
#pragma unroll
    for (int j = 0; j < 4; j++)
        t[ty + 8 * j][tx] = x[(b * CC + c0 + ty + 8 * j) * HWD + hw0 + tx];
    __syncthreads();
    __half2* outp = (__half2*)g_xH;
#pragma unroll
    for (int idx = tid; idx < 512; idx += 256) {
        int hwl = idx >> 4, cp = idx & 15;
        __half2 v = __floats2half2_rn(t[2 * cp][hwl], t[2 * cp + 1][hwl]);
        outp[((size_t)(b * HWD + hw0 + hwl) * CC + c0) / 2 + cp] = v;
    }
}

// ---------------- k1: transpose Wp (padded) + zero stats --------------------
__global__ void k_prep(const float* __restrict__ Wp) {
    int idx = blockIdx.x * blockDim.x + threadIdx.x;
    if (idx < CC * 9 * WSP) {
        int ci = idx / (9 * WSP);
        int rem = idx % (9 * WSP);
        int tap = rem / WSP;
        int k = rem % WSP;
        g_Wt[idx] = (k < K54) ? Wp[(k * CC + ci) * 9 + tap] : 0.f;
    }
    if (idx < NS * CC) { g_sum[idx] = 0.f; g_sumsq[idx] = 0.f; }
}

// ---------------- k2: 3x3 offset conv, cp.async double-buffered -------------
__global__ void __launch_bounds__(128) k_conv(const float* __restrict__ x,
                                              const float* __restrict__ bp) {
    __shared__ float xs[2][3 * 132];   // rows h-1..h+1, padded cols
    __shared__ float ws[2][9 * WSP];   // [tap][k54] pitch 56
    int b = blockIdx.y;
    int h = blockIdx.x;
    int w = threadIdx.x;

    unsigned xs_s[2], ws_s[2];
    xs_s[0] = (unsigned)__cvta_generic_to_shared(&xs[0][0]);
    xs_s[1] = (unsigned)__cvta_generic_to_shared(&xs[1][0]);
    ws_s[0] = (unsigned)__cvta_generic_to_shared(&ws[0][0]);
    ws_s[1] = (unsigned)__cvta_generic_to_shared(&ws[1][0]);

    const float* xb = x + (size_t)b * CC * HWD;

    auto prefetch = [&](int ci, int bi) {
        const float* xc = xb + (size_t)ci * HWD;
#pragma unroll
        for (int it = 0; it < 4; it++) {
            int idx = w + it * 128;
            if (idx < 396) {
                int r = idx / 132, cw = idx % 132 - 1;
                int hh = h - 1 + r;
                bool valid = (hh >= 0) & (hh < HH) & (cw >= 0) & (cw < WW);
                const float* gp = xc + min(max(hh, 0), HH - 1) * WW + min(max(cw, 0), WW - 1);
                cpa4(xs_s[bi] + idx * 4, gp, valid);
            }
        }
        if (w < 126)
            cpa16(ws_s[bi] + w * 16, &g_Wt[ci * 9 * WSP + w * 4]);
    };

    float acc[K54];
#pragma unroll
    for (int k = 0; k < K54; k++) acc[k] = 0.f;

    prefetch(0, 0);
    cpa_commit();

    for (int ci = 0; ci < CC; ci++) {
        int bi = ci & 1;
        __syncthreads();
        if (ci + 1 < CC) {
            prefetch(ci + 1, bi ^ 1);
            cpa_commit();
            cpa_wait<1>();
        } else {
            cpa_wait<0>();
        }
        __syncthreads();

        float xv[9];
#pragma unroll
        for (int dh = 0; dh < 3; dh++)
#pragma unroll
            for (int dw = 0; dw < 3; dw++)
                xv[dh * 3 + dw] = xs[bi][dh * 132 + w + dw];
#pragma unroll
        for (int tap = 0; tap < 9; tap++) {
            float a = xv[tap];
            const float4* wr = (const float4*)&ws[bi][tap * WSP];
#pragma unroll
            for (int k4 = 0; k4 < 13; k4++) {
                float4 wv = wr[k4];
                int k = k4 * 4;
                acc[k + 0] = fmaf(a, wv.x, acc[k + 0]);
                acc[k + 1] = fmaf(a, wv.y, acc[k + 1]);
                acc[k + 2] = fmaf(a, wv.z, acc[k + 2]);
                acc[k + 3] = fmaf(a, wv.w, acc[k + 3]);
            }
            acc[52] = fmaf(a, ws[bi][tap * WSP + 52], acc[52]);
            acc[53] = fmaf(a, ws[bi][tap * WSP + 53], acc[53]);
        }
    }
    float* op = g_off + ((size_t)b * HWD + h * WW + w) * K54;
#pragma unroll
    for (int k = 0; k < K54; k++) {
        float sc = (k < 18) ? 1.f : ((k < 36) ? 2.f : 3.f);
        op[k] = (acc[k] + bp[k]) * sc;
    }
}

// ---------------- k3: cp.async-pipelined gather + bilinear + GEMM + stats ---
// block = 256 thr, 32 pixels; 8 lanes/pixel.
// Phase A: per-point cp.async (4x16B corners) into a 4-slot smem ring; each
//          thread consumes only its own staged bytes -> no sync in pipeline.
// Phase B: 64x64 GEMM from smem (runs under nothing now, but cheap).
extern __shared__ __align__(16) unsigned char dynsm[];
__global__ void __launch_bounds__(256, 2) k_gather(const float* __restrict__ WcG) {
    float* Wc_sh  = (float*)dynsm;                 // [c][o]
    float* xoff   = Wc_sh + SM_WC_F;               // [p][c] pitch 65
    float* off_sh = xoff + SM_XOFF_F;              // [p][18] pitch 19
    unsigned char* stage = (unsigned char*)(off_sh + SM_OFF_F);

    int h = blockIdx.x >> 2;
    int w0 = (blockIdx.x & 3) * 32;
    int b = blockIdx.y, s = blockIdx.z;
    int tid = threadIdx.x;

    for (int idx = tid; idx < 4096; idx += 256) {
        int o = idx >> 6, c = idx & 63;
        Wc_sh[c * 64 + o] = WcG[s * 4096 + idx];   // Wc[o][c] -> [c][o]
    }
    {
        const float* ob = g_off + ((size_t)(b * HWD + h * WW + w0)) * K54 + s * 18;
        for (int idx = tid; idx < 32 * 18; idx += 256) {
            int p = idx / 18, j = idx % 18;
            off_sh[p * 19 + j] = ob[p * K54 + j];
        }
    }
    __syncthreads();

    const __half* xHb = g_xH + (size_t)b * HWD * CC;
    const float inv9 = 1.f / 9.f;

    int p = tid >> 3;                  // 0..31
    int l = tid & 7;                   // channel octet
    const float* offp = &off_sh[p * 19];

    int raws[9]; float fxs[9], fys[9];
#pragma unroll
    for (int n = 0; n < 9; n++) {
        float px = (float)(h + n / 3) + offp[n];
        float py = (float)(w0 + p + n % 3) + offp[9 + n];
        float flx = floorf(px), fly = floorf(py);
        fxs[n] = px - flx; fys[n] = py - fly;
        raws[n] = (int)(flx * 128.f + fly);
    }

    unsigned my_u = (unsigned)__cvta_generic_to_shared(stage) + (unsigned)(p * 512 + l * 16);
    const unsigned char* my_c = stage + p * 512 + l * 16;

    auto issue = [&](int n) {
        int raw = raws[n];
        int i0 = min(max(raw, 0), HWD - 1);
        int i1 = min(max(raw + 1, 0), HWD - 1);
        int i2 = min(max(raw + 128, 0), HWD - 1);
        int i3 = min(max(raw + 129, 0), HWD - 1);
        unsigned d = my_u + (unsigned)((n & 3) * 16384);
        cpa16ca(d,       xHb + (size_t)i0 * CC + l * 8);
        cpa16ca(d + 128, xHb + (size_t)i1 * CC + l * 8);
        cpa16ca(d + 256, xHb + (size_t)i2 * CC + l * 8);
        cpa16ca(d + 384, xHb + (size_t)i3 * CC + l * 8);
        cpa_commit();
    };

    float acc[8];
#pragma unroll
    for (int j = 0; j < 8; j++) acc[j] = 0.f;

    auto consume = [&](int n) {
        float fx = fxs[n], fy = fys[n];
        float wlt = (1.f - fx) * (1.f - fy);
        float wrb = fx * fy;
        float wlb = (1.f - fx) * fy;       // corner raw+1
        float wrt = fx * (1.f - fy);       // corner raw+128
        const uint4* st = (const uint4*)(my_c + (n & 3) * 16384);
        uint4 v0 = st[0];    // corner i0 (+0)
        uint4 v1 = st[8];    // corner i1 (+128B)
        uint4 v2 = st[16];   // corner i2 (+256B)
        uint4 v3 = st[24];   // corner i3 (+384B)
        const __half2* h0 = (const __half2*)&v0;
        const __half2* h1 = (const __half2*)&v1;
        const __half2* h2 = (const __half2*)&v2;
        const __half2* h3 = (const __half2*)&v3;
#pragma unroll
        for (int k = 0; k < 4; k++) {
            float2 f0 = __half22float2(h0[k]);
            float2 f1 = __half22float2(h1[k]);
            float2 f2 = __half22float2(h2[k]);
            float2 f3 = __half22float2(h3[k]);
            acc[2 * k + 0] = fmaf(wlt, f0.x, acc[2 * k + 0]);
            acc[2 * k + 1] = fmaf(wlt, f0.y, acc[2 * k + 1]);
            acc[2 * k + 0] = fmaf(wlb, f1.x, acc[2 * k + 0]);
            acc[2 * k + 1] = fmaf(wlb, f1.y, acc[2 * k + 1]);
            acc[2 * k + 0] = fmaf(wrt, f2.x, acc[2 * k + 0]);
            acc[2 * k + 1] = fmaf(wrt, f2.y, acc[2 * k + 1]);
            acc[2 * k + 0] = fmaf(wrb, f3.x, acc[2 * k + 0]);
            acc[2 * k + 1] = fmaf(wrb, f3.y, acc[2 * k + 1]);
        }
    };

    // 4-slot ring, commit group per point, per-thread completion only
    issue(0); issue(1); issue(2);
#pragma unroll
    for (int n = 0; n < 6; n++) {
        issue(n + 3);
        cpa_wait<3>();
        consume(n);
    }
    cpa_wait<2>(); consume(6);
    cpa_wait<1>(); consume(7);
    cpa_wait<0>(); consume(8);

#pragma unroll
    for (int j = 0; j < 8; j++) xoff[p * 65 + l * 8 + j] = acc[j] * inv9;
    __syncthreads();

    // Phase B: y[p][o] = sum_c xoff[p][c] * Wc[o][c], 8 outs/thread
    int p2 = tid & 31;
    int obase = (tid >> 5) * 8;
    float acc2[8];
#pragma unroll
    for (int q = 0; q < 8; q++) acc2[q] = 0.f;
    for (int c = 0; c < 64; c++) {
        float xv = xoff[p2 * 65 + c];
        const float4* w4 = (const float4*)&Wc_sh[c * 64 + obase];
        float4 wa = w4[0], wb = w4[1];
        acc2[0] = fmaf(xv, wa.x, acc2[0]);
        acc2[1] = fmaf(xv, wa.y, acc2[1]);
        acc2[2] = fmaf(xv, wa.z, acc2[2]);
        acc2[3] = fmaf(xv, wa.w, acc2[3]);
        acc2[4] = fmaf(xv, wb.x, acc2[4]);
        acc2[5] = fmaf(xv, wb.y, acc2[5]);
        acc2[6] = fmaf(xv, wb.z, acc2[6]);
        acc2[7] = fmaf(xv, wb.w, acc2[7]);
    }
    float* yb = g_y + ((size_t)(s * BB + b) * CC) * HWD + h * WW + w0;
#pragma unroll
    for (int q = 0; q < 8; q++) yb[(size_t)(obase + q) * HWD + p2] = acc2[q];

    // BN partial stats: within a warp all lanes share obase, distinct p
    int lane = tid & 31;
#pragma unroll
    for (int q = 0; q < 8; q++) {
        float v = acc2[q], v2 = v * v;
#pragma unroll
        for (int ofs = 16; ofs > 0; ofs >>= 1) {
            v += __shfl_down_sync(0xffffffffu, v, ofs);
            v2 += __shfl_down_sync(0xffffffffu, v2, ofs);
        }
        if (lane == 0) {
            atomicAdd(&g_sum[s * CC + obase + q], v);
            atomicAdd(&g_sumsq[s * CC + obase + q], v2);
        }
    }
}

// ---------------- k4: finalize BN coefficients ------------------------------
__global__ void k_stats(const float* __restrict__ gamma, const float* __restrict__ beta) {
    int t = threadIdx.x;
    if (t < NS * CC) {
        float inv = 1.f / CNT;
        float mu = g_sum[t] * inv;
        float var = g_sumsq[t] * inv - mu * mu;
        float A = gamma[t] * rsqrtf(var + BN_EPS);
        g_AB[t * 2] = A;
        g_AB[t * 2 + 1] = beta[t] - mu * A;
    }
}

// ---------------- k5: normalize + SiLU + average scales ---------------------
__global__ void k_final(float* __restrict__ out) {
    int idx = blockIdx.x * blockDim.x + threadIdx.x;   // over B*C*HWD
    int o = (idx >> 14) & 63;
    float r = 0.f;
#pragma unroll
    for (int s = 0; s < NS; s++) {
        float v = g_y[(size_t)s * BB * CC * HWD + idx];
        int t = s * CC + o;
        float yn = fmaf(v, g_AB[t * 2], g_AB[t * 2 + 1]);
        r += yn / (1.f + expf(-yn));
    }
    out[idx] = r * (1.f / 3.f);
}

// ---------------- launch ----------------------------------------------------
extern "C" void kernel_launch(void* const* d_in, const int* in_sizes, int n_in,
                              void* d_out, int out_size) {
    const float* x     = (const float*)d_in[0];
    const float* Wp    = (const float*)d_in[1];
    const float* bp    = (const float*)d_in[2];
    const float* Wc    = (const float*)d_in[3];
    const float* gamma = (const float*)d_in[4];
    const float* beta  = (const float*)d_in[5];
    float* out = (float*)d_out;

    cudaFuncSetAttribute(k_gather, cudaFuncAttributeMaxDynamicSharedMemorySize, SM_TOTAL_B);

    dim3 tb(32, 8);
    dim3 tg(HWD / 32, CC / 32, BB);
    k_transpose<<<tg, tb>>>(x);
    k_prep<<<((CC * 9 * WSP) + 255) / 256, 256>>>(Wp);
    k_conv<<<dim3(HH, BB), 128>>>(x, bp);
    k_gather<<<dim3(HH * 4, BB, NS), 256, SM_TOTAL_B>>>(Wc);
    k_stats<<<1, 256>>>(gamma, beta);
    k_final<<<(BB * CC * HWD) / 256, 256>>>(out);
}

// round 11
// speedup vs baseline: 1.2232x; 1.0201x over previous
#include <cuda_runtime.h>
#include <cuda_fp16.h>
#include <cstdint>
#include <math.h>

#define BB 8
#define CC 64
#define HH 128
#define WW 128
#define HWD 16384
#define NS 3
#define K54 54
#define WSP 56                      // padded weight pitch (floats) per tap
#define CNT 131072.0f
#define BN_EPS 1e-5f

// ---------------- scratch (device globals; no runtime allocation) ----------
__device__ __half g_xH[BB * HWD * CC];         // x as [b][hw][c] fp16 (16.8 MB)
__device__ float g_off[BB * HWD * K54];        // offsets channel-last (28.3 MB)
__device__ float g_Wt[CC * 9 * WSP];           // Wp as [ci][tap][k54 padded to 56]
__device__ __half g_yH[NS * BB * CC * HWD];    // pre-BN y fp16 [s][b][o][hw] (50 MB)
__device__ float g_sum[NS * CC];
__device__ float g_sumsq[NS * CC];
__device__ float g_AB[NS * CC * 2];            // A = gamma*rsqrt(var+eps), B = beta-mu*A

// ---------------- cp.async helpers -----------------------------------------
__device__ __forceinline__ void cpa4(unsigned s, const void* g, bool v) {
    asm volatile("cp.async.ca.shared.global [%0], [%1], 4, %2;"
                 :: "r"(s), "l"(g), "r"(v ? 4u : 0u));
}
__device__ __forceinline__ void cpa16(unsigned s, const void* g) {
    asm volatile("cp.async.cg.shared.global [%0], [%1], 16;" :: "r"(s), "l"(g));
}
__device__ __forceinline__ void cpa_commit() {
    asm volatile("cp.async.commit_group;");
}
template <int N>
__device__ __forceinline__ void cpa_wait() {
    asm volatile("cp.async.wait_group %0;" :: "n"(N));
}

// ---------------- k0: transpose x (b,c,hw) -> (b,hw,c) fp16 ----------------
__global__ void k_transpose(const float* __restrict__ x) {
    __shared__ float t[32][33];                // t[c_local][hw_local]
    int b = blockIdx.z;
    int hw0 = blockIdx.x * 32;
    int c0 = blockIdx.y * 32;
    int tx = threadIdx.x, ty = threadIdx.y;   // (32, 8)
    int tid = ty * 32 + tx;
#pragma unroll
    for (int j = 0; j < 4; j++)
        t[ty + 8 * j][tx] = x[(b * CC + c0 + ty + 8 * j) * HWD + hw0 + tx];
    __syncthreads();
    __half2* outp = (__half2*)g_xH;
#pragma unroll
    for (int idx = tid; idx < 512; idx += 256) {
        int hwl = idx >> 4, cp = idx & 15;
        __half2 v = __floats2half2_rn(t[2 * cp][hwl], t[2 * cp + 1][hwl]);
        outp[((size_t)(b * HWD + hw0 + hwl) * CC + c0) / 2 + cp] = v;
    }
}

// ---------------- k1: transpose Wp (padded) + zero stats --------------------
__global__ void k_prep(const float* __restrict__ Wp) {
    int idx = blockIdx.x * blockDim.x + threadIdx.x;
    if (idx < CC * 9 * WSP) {
        int ci = idx / (9 * WSP);
        int rem = idx % (9 * WSP);
        int tap = rem / WSP;
        int k = rem % WSP;
        g_Wt[idx] = (k < K54) ? Wp[(k * CC + ci) * 9 + tap] : 0.f;
    }
    if (idx < NS * CC) { g_sum[idx] = 0.f; g_sumsq[idx] = 0.f; }
}

// ---------------- k2: 3x3 offset conv, cp.async double-buffered -------------
__global__ void __launch_bounds__(128) k_conv(const float* __restrict__ x,
                                              const float* __restrict__ bp) {
    __shared__ float xs[2][3 * 132];   // rows h-1..h+1, padded cols
    __shared__ float ws[2][9 * WSP];   // [tap][k54] pitch 56
    int b = blockIdx.y;
    int h = blockIdx.x;
    int w = threadIdx.x;

    unsigned xs_s[2], ws_s[2];
    xs_s[0] = (unsigned)__cvta_generic_to_shared(&xs[0][0]);
    xs_s[1] = (unsigned)__cvta_generic_to_shared(&xs[1][0]);
    ws_s[0] = (unsigned)__cvta_generic_to_shared(&ws[0][0]);
    ws_s[1] = (unsigned)__cvta_generic_to_shared(&ws[1][0]);

    const float* xb = x + (size_t)b * CC * HWD;

    auto prefetch = [&](int ci, int bi) {
        const float* xc = xb + (size_t)ci * HWD;
#pragma unroll
        for (int it = 0; it < 4; it++) {
            int idx = w + it * 128;
            if (idx < 396) {
                int r = idx / 132, cw = idx % 132 - 1;
                int hh = h - 1 + r;
                bool valid = (hh >= 0) & (hh < HH) & (cw >= 0) & (cw < WW);
                const float* gp = xc + min(max(hh, 0), HH - 1) * WW + min(max(cw, 0), WW - 1);
                cpa4(xs_s[bi] + idx * 4, gp, valid);
            }
        }
        if (w < 126)
            cpa16(ws_s[bi] + w * 16, &g_Wt[ci * 9 * WSP + w * 4]);
    };

    float acc[K54];
#pragma unroll
    for (int k = 0; k < K54; k++) acc[k] = 0.f;

    prefetch(0, 0);
    cpa_commit();

    for (int ci = 0; ci < CC; ci++) {
        int bi = ci & 1;
        __syncthreads();
        if (ci + 1 < CC) {
            prefetch(ci + 1, bi ^ 1);
            cpa_commit();
            cpa_wait<1>();
        } else {
            cpa_wait<0>();
        }
        __syncthreads();

        float xv[9];
#pragma unroll
        for (int dh = 0; dh < 3; dh++)
#pragma unroll
            for (int dw = 0; dw < 3; dw++)
                xv[dh * 3 + dw] = xs[bi][dh * 132 + w + dw];
#pragma unroll
        for (int tap = 0; tap < 9; tap++) {
            float a = xv[tap];
            const float4* wr = (const float4*)&ws[bi][tap * WSP];
#pragma unroll
            for (int k4 = 0; k4 < 13; k4++) {
                float4 wv = wr[k4];
                int k = k4 * 4;
                acc[k + 0] = fmaf(a, wv.x, acc[k + 0]);
                acc[k + 1] = fmaf(a, wv.y, acc[k + 1]);
                acc[k + 2] = fmaf(a, wv.z, acc[k + 2]);
                acc[k + 3] = fmaf(a, wv.w, acc[k + 3]);
            }
            acc[52] = fmaf(a, ws[bi][tap * WSP + 52], acc[52]);
            acc[53] = fmaf(a, ws[bi][tap * WSP + 53], acc[53]);
        }
    }
    float* op = g_off + ((size_t)b * HWD + h * WW + w) * K54;
#pragma unroll
    for (int k = 0; k < K54; k++) {
        float sc = (k < 18) ? 1.f : ((k < 36) ? 2.f : 3.f);
        op[k] = (acc[k] + bp[k]) * sc;
    }
}

// ---------------- k3: gather + HFMA2 bilinear + GEMM + stats ----------------
// block = 256 thr, 32 pixels of one (s,b,h) quarter-row; 8 lanes/pixel.
// Corner blend in half2 (4 HFMA2 / 2ch), point accumulation in fp32.
__global__ void __launch_bounds__(256, 3) k_gather(const float* __restrict__ WcG) {
    __shared__ float Wc_sh[64 * 64];      // [c][o]
    __shared__ float xoff[32 * 65];       // [p][c] pitch 65
    __shared__ float off_sh[32 * 19];     // [p][18] pitch 19

    int h = blockIdx.x >> 2;
    int w0 = (blockIdx.x & 3) * 32;
    int b = blockIdx.y, s = blockIdx.z;
    int tid = threadIdx.x;

    for (int idx = tid; idx < 4096; idx += 256) {
        int o = idx >> 6, c = idx & 63;
        Wc_sh[c * 64 + o] = WcG[s * 4096 + idx];   // Wc[o][c] -> [c][o]
    }
    {
        const float* ob = g_off + ((size_t)(b * HWD + h * WW + w0)) * K54 + s * 18;
        for (int idx = tid; idx < 32 * 18; idx += 256) {
            int p = idx / 18, j = idx % 18;
            off_sh[p * 19 + j] = ob[p * K54 + j];
        }
    }
    __syncthreads();

    const __half* xHb = g_xH + (size_t)b * HWD * CC;
    const float inv9 = 1.f / 9.f;
    {
        int p = tid >> 3;                  // 0..31
        int l = tid & 7;                   // channel octet
        const float* offp = &off_sh[p * 19];

        int raws[9]; float fxs[9], fys[9];
#pragma unroll
        for (int n = 0; n < 9; n++) {
            float px = (float)(h + n / 3) + offp[n];
            float py = (float)(w0 + p + n % 3) + offp[9 + n];
            float flx = floorf(px), fly = floorf(py);
            fxs[n] = px - flx; fys[n] = py - fly;
            raws[n] = (int)(flx * 128.f + fly);
        }

        float acc[8];
#pragma unroll
        for (int j = 0; j < 8; j++) acc[j] = 0.f;
#pragma unroll
        for (int n = 0; n < 9; n++) {
            int raw = raws[n];
            float fx = fxs[n], fy = fys[n];
            __half2 wltH = __float2half2_rn((1.f - fx) * (1.f - fy));
            __half2 wrbH = __float2half2_rn(fx * fy);
            __half2 wlbH = __float2half2_rn((1.f - fx) * fy);       // corner raw+1
            __half2 wrtH = __float2half2_rn(fx * (1.f - fy));       // corner raw+128
            int i0 = min(max(raw, 0), HWD - 1);
            int i1 = min(max(raw + 1, 0), HWD - 1);
            int i2 = min(max(raw + 128, 0), HWD - 1);
            int i3 = min(max(raw + 129, 0), HWD - 1);
            uint4 v0 = *(const uint4*)(xHb + (size_t)i0 * CC + l * 8);
            uint4 v1 = *(const uint4*)(xHb + (size_t)i1 * CC + l * 8);
            uint4 v2 = *(const uint4*)(xHb + (size_t)i2 * CC + l * 8);
            uint4 v3 = *(const uint4*)(xHb + (size_t)i3 * CC + l * 8);
            const __half2* h0 = (const __half2*)&v0;
            const __half2* h1 = (const __half2*)&v1;
            const __half2* h2 = (const __half2*)&v2;
            const __half2* h3 = (const __half2*)&v3;
#pragma unroll
            for (int k = 0; k < 4; k++) {
                __half2 hv = __hmul2(h0[k], wltH);
                hv = __hfma2(h1[k], wlbH, hv);
                hv = __hfma2(h2[k], wrtH, hv);
                hv = __hfma2(h3[k], wrbH, hv);
                float2 f = __half22float2(hv);
                acc[2 * k + 0] += f.x;
                acc[2 * k + 1] += f.y;
            }
        }
#pragma unroll
        for (int j = 0; j < 8; j++) xoff[p * 65 + l * 8 + j] = acc[j] * inv9;
    }
    __syncthreads();

    // Phase B: y[p][o] = sum_c xoff[p][c] * Wc[o][c], 8 outs/thread (fp32)
    int p2 = tid & 31;
    int obase = (tid >> 5) * 8;
    float acc2[8];
#pragma unroll
    for (int q = 0; q < 8; q++) acc2[q] = 0.f;
    for (int c = 0; c < 64; c++) {
        float xv = xoff[p2 * 65 + c];
        const float4* w4 = (const float4*)&Wc_sh[c * 64 + obase];
        float4 wa = w4[0], wb = w4[1];
        acc2[0] = fmaf(xv, wa.x, acc2[0]);
        acc2[1] = fmaf(xv, wa.y, acc2[1]);
        acc2[2] = fmaf(xv, wa.z, acc2[2]);
        acc2[3] = fmaf(xv, wa.w, acc2[3]);
        acc2[4] = fmaf(xv, wb.x, acc2[4]);
        acc2[5] = fmaf(xv, wb.y, acc2[5]);
        acc2[6] = fmaf(xv, wb.z, acc2[6]);
        acc2[7] = fmaf(xv, wb.w, acc2[7]);
    }
    __half* yb = g_yH + ((size_t)(s * BB + b) * CC) * HWD + h * WW + w0;
#pragma unroll
    for (int q = 0; q < 8; q++)
        yb[(size_t)(obase + q) * HWD + p2] = __float2half_rn(acc2[q]);

    // BN partial stats from fp32 values: warp over 32 pixels
    int lane = tid & 31;
#pragma unroll
    for (int q = 0; q < 8; q++) {
        float v = acc2[q], v2 = v * v;
#pragma unroll
        for (int ofs = 16; ofs > 0; ofs >>= 1) {
            v += __shfl_down_sync(0xffffffffu, v, ofs);
            v2 += __shfl_down_sync(0xffffffffu, v2, ofs);
        }
        if (lane == 0) {
            atomicAdd(&g_sum[s * CC + obase + q], v);
            atomicAdd(&g_sumsq[s * CC + obase + q], v2);
        }
    }
}

// ---------------- k4: finalize BN coefficients ------------------------------
__global__ void k_stats(const float* __restrict__ gamma, const float* __restrict__ beta) {
    int t = threadIdx.x;
    if (t < NS * CC) {
        float inv = 1.f / CNT;
        float mu = g_sum[t] * inv;
        float var = g_sumsq[t] * inv - mu * mu;
        float A = gamma[t] * rsqrtf(var + BN_EPS);
        g_AB[t * 2] = A;
        g_AB[t * 2 + 1] = beta[t] - mu * A;
    }
}

// ---------------- k5: normalize + SiLU + average scales ---------------------
__global__ void k_final(float* __restrict__ out) {
    int idx = blockIdx.x * blockDim.x + threadIdx.x;   // over B*C*HWD
    int o = (idx >> 14) & 63;
    float r = 0.f;
#pragma unroll
    for (int s = 0; s < NS; s++) {
        float v = __half2float(g_yH[(size_t)s * BB * CC * HWD + idx]);
        int t = s * CC + o;
        float yn = fmaf(v, g_AB[t * 2], g_AB[t * 2 + 1]);
        r += yn / (1.f + expf(-yn));
    }
    out[idx] = r * (1.f / 3.f);
}

// ---------------- launch ----------------------------------------------------
extern "C" void kernel_launch(void* const* d_in, const int* in_sizes, int n_in,
                              void* d_out, int out_size) {
    const float* x     = (const float*)d_in[0];
    const float* Wp    = (const float*)d_in[1];
    const float* bp    = (const float*)d_in[2];
    const float* Wc    = (const float*)d_in[3];
    const float* gamma = (const float*)d_in[4];
    const float* beta  = (const float*)d_in[5];
    float* out = (float*)d_out;

    dim3 tb(32, 8);
    dim3 tg(HWD / 32, CC / 32, BB);
    k_transpose<<<tg, tb>>>(x);
    k_prep<<<((CC * 9 * WSP) + 255) / 256, 256>>>(Wp);
    k_conv<<<dim3(HH, BB), 128>>>(x, bp);
    k_gather<<<dim3(HH * 4, BB, NS), 256>>>(Wc);
    k_stats<<<1, 256>>>(gamma, beta);
    k_final<<<(BB * CC * HWD) / 256, 256>>>(out);
}

// round 12
// speedup vs baseline: 1.2315x; 1.0067x over previous
#include <cuda_runtime.h>
#include <cuda_fp16.h>
#include <cstdint>
#include <math.h>

#define BB 8
#define CC 64
#define HH 128
#define WW 128
#define HWD 16384
#define NS 3
#define K54 54
#define WSP 56                      // padded weight pitch (floats) per tap
#define CNT 131072.0f
#define BN_EPS 1e-5f

// ---------------- scratch (device globals; no runtime allocation) ----------
__device__ __half g_xH[BB * HWD * CC];         // x as [b][hw][c] fp16 (16.8 MB)
__device__ float g_off[BB * HWD * K54];        // offsets channel-last (28.3 MB)
__device__ float g_Wt[CC * 9 * WSP];           // Wp as [ci][tap][k54 padded to 56]
__device__ __half g_yH[NS * BB * CC * HWD];    // pre-BN y fp16 [s][b][o][hw] (50 MB)
__device__ float g_sum[NS * CC];
__device__ float g_sumsq[NS * CC];
__device__ float g_AB[NS * CC * 2];            // A = gamma*rsqrt(var+eps), B = beta-mu*A

// ---------------- cp.async helpers -----------------------------------------
__device__ __forceinline__ void cpa4(unsigned s, const void* g, bool v) {
    asm volatile("cp.async.ca.shared.global [%0], [%1], 4, %2;"
                 :: "r"(s), "l"(g), "r"(v ? 4u : 0u));
}
__device__ __forceinline__ void cpa16(unsigned s, const void* g) {
    asm volatile("cp.async.cg.shared.global [%0], [%1], 16;" :: "r"(s), "l"(g));
}
__device__ __forceinline__ void cpa_commit() {
    asm volatile("cp.async.commit_group;");
}
template <int N>
__device__ __forceinline__ void cpa_wait() {
    asm volatile("cp.async.wait_group %0;" :: "n"(N));
}

// ---------------- k0: transpose x (b,c,hw) -> (b,hw,c) fp16 ----------------
__global__ void k_transpose(const float* __restrict__ x) {
    __shared__ float t[32][33];                // t[c_local][hw_local]
    int b = blockIdx.z;
    int hw0 = blockIdx.x * 32;
    int c0 = blockIdx.y * 32;
    int tx = threadIdx.x, ty = threadIdx.y;   // (32, 8)
    int tid = ty * 32 + tx;
#pragma unroll
    for (int j = 0; j < 4; j++)
        t[ty + 8 * j][tx] = x[(b * CC + c0 + ty + 8 * j) * HWD + hw0 + tx];
    __syncthreads();
    __half2* outp = (__half2*)g_xH;
#pragma unroll
    for (int idx = tid; idx < 512; idx += 256) {
        int hwl = idx >> 4, cp = idx & 15;
        __half2 v = __floats2half2_rn(t[2 * cp][hwl], t[2 * cp + 1][hwl]);
        outp[((size_t)(b * HWD + hw0 + hwl) * CC + c0) / 2 + cp] = v;
    }
}

// ---------------- k1: transpose Wp (padded) + zero stats --------------------
__global__ void k_prep(const float* __restrict__ Wp) {
    int idx = blockIdx.x * blockDim.x + threadIdx.x;
    if (idx < CC * 9 * WSP) {
        int ci = idx / (9 * WSP);
        int rem = idx % (9 * WSP);
        int tap = rem / WSP;
        int k = rem % WSP;
        g_Wt[idx] = (k < K54) ? Wp[(k * CC + ci) * 9 + tap] : 0.f;
    }
    if (idx < NS * CC) { g_sum[idx] = 0.f; g_sumsq[idx] = 0.f; }
}

// ---------------- k2: 3x3 offset conv, cp.async double-buffered -------------
__global__ void __launch_bounds__(128) k_conv(const float* __restrict__ x,
                                              const float* __restrict__ bp) {
    __shared__ float xs[2][3 * 132];   // rows h-1..h+1, padded cols
    __shared__ float ws[2][9 * WSP];   // [tap][k54] pitch 56
    int b = blockIdx.y;
    int h = blockIdx.x;
    int w = threadIdx.x;

    unsigned xs_s[2], ws_s[2];
    xs_s[0] = (unsigned)__cvta_generic_to_shared(&xs[0][0]);
    xs_s[1] = (unsigned)__cvta_generic_to_shared(&xs[1][0]);
    ws_s[0] = (unsigned)__cvta_generic_to_shared(&ws[0][0]);
    ws_s[1] = (unsigned)__cvta_generic_to_shared(&ws[1][0]);

    const float* xb = x + (size_t)b * CC * HWD;

    auto prefetch = [&](int ci, int bi) {
        const float* xc = xb + (size_t)ci * HWD;
#pragma unroll
        for (int it = 0; it < 4; it++) {
            int idx = w + it * 128;
            if (idx < 396) {
                int r = idx / 132, cw = idx % 132 - 1;
                int hh = h - 1 + r;
                bool valid = (hh >= 0) & (hh < HH) & (cw >= 0) & (cw < WW);
                const float* gp = xc + min(max(hh, 0), HH - 1) * WW + min(max(cw, 0), WW - 1);
                cpa4(xs_s[bi] + idx * 4, gp, valid);
            }
        }
        if (w < 126)
            cpa16(ws_s[bi] + w * 16, &g_Wt[ci * 9 * WSP + w * 4]);
    };

    float acc[K54];
#pragma unroll
    for (int k = 0; k < K54; k++) acc[k] = 0.f;

    prefetch(0, 0);
    cpa_commit();

    for (int ci = 0; ci < CC; ci++) {
        int bi = ci & 1;
        __syncthreads();
        if (ci + 1 < CC) {
            prefetch(ci + 1, bi ^ 1);
            cpa_commit();
            cpa_wait<1>();
        } else {
            cpa_wait<0>();
        }
        __syncthreads();

        float xv[9];
#pragma unroll
        for (int dh = 0; dh < 3; dh++)
#pragma unroll
            for (int dw = 0; dw < 3; dw++)
                xv[dh * 3 + dw] = xs[bi][dh * 132 + w + dw];
#pragma unroll
        for (int tap = 0; tap < 9; tap++) {
            float a = xv[tap];
            const float4* wr = (const float4*)&ws[bi][tap * WSP];
#pragma unroll
            for (int k4 = 0; k4 < 13; k4++) {
                float4 wv = wr[k4];
                int k = k4 * 4;
                acc[k + 0] = fmaf(a, wv.x, acc[k + 0]);
                acc[k + 1] = fmaf(a, wv.y, acc[k + 1]);
                acc[k + 2] = fmaf(a, wv.z, acc[k + 2]);
                acc[k + 3] = fmaf(a, wv.w, acc[k + 3]);
            }
            acc[52] = fmaf(a, ws[bi][tap * WSP + 52], acc[52]);
            acc[53] = fmaf(a, ws[bi][tap * WSP + 53], acc[53]);
        }
    }
    float* op = g_off + ((size_t)b * HWD + h * WW + w) * K54;
#pragma unroll
    for (int k = 0; k < K54; k++) {
        float sc = (k < 18) ? 1.f : ((k < 36) ? 2.f : 3.f);
        op[k] = (acc[k] + bp[k]) * sc;
    }
}

// ---------------- k3: gather + HFMA2 bilinear + GEMM + stats ----------------
// block = 256 thr, 32 pixels; 8 lanes/pixel.
// Wc_sh stored AS-READ ([o][c], conflict-free); phase B reads it via
// warp-uniform broadcasts. xoff pitch 68 for aligned float4, conflict-free.
__global__ void __launch_bounds__(256, 3) k_gather(const float* __restrict__ WcG) {
    __shared__ float Wc_sh[64 * 64];      // [o][c]  (straight copy)
    __shared__ float xoff[32 * 68];       // [p][c] pitch 68
    __shared__ float off_sh[32 * 19];     // [p][18] pitch 19

    int h = blockIdx.x >> 2;
    int w0 = (blockIdx.x & 3) * 32;
    int b = blockIdx.y, s = blockIdx.z;
    int tid = threadIdx.x;

    // conflict-free straight copy: Wc_sh[o*64+c]
    {
        const float4* src = (const float4*)(WcG + s * 4096);
        float4* dst = (float4*)Wc_sh;
        for (int idx = tid; idx < 1024; idx += 256) dst[idx] = src[idx];
    }
    {
        const float* ob = g_off + ((size_t)(b * HWD + h * WW + w0)) * K54 + s * 18;
        for (int idx = tid; idx < 32 * 18; idx += 256) {
            int p = idx / 18, j = idx % 18;
            off_sh[p * 19 + j] = ob[p * K54 + j];
        }
    }
    __syncthreads();

    const __half* xHb = g_xH + (size_t)b * HWD * CC;
    const float inv9 = 1.f / 9.f;
    {
        int p = tid >> 3;                  // 0..31
        int l = tid & 7;                   // channel octet
        const float* offp = &off_sh[p * 19];

        int raws[9]; float fxs[9], fys[9];
#pragma unroll
        for (int n = 0; n < 9; n++) {
            float px = (float)(h + n / 3) + offp[n];
            float py = (float)(w0 + p + n % 3) + offp[9 + n];
            float flx = floorf(px), fly = floorf(py);
            fxs[n] = px - flx; fys[n] = py - fly;
            raws[n] = (int)(flx * 128.f + fly);
        }

        float acc[8];
#pragma unroll
        for (int j = 0; j < 8; j++) acc[j] = 0.f;
#pragma unroll
        for (int n = 0; n < 9; n++) {
            int raw = raws[n];
            float fx = fxs[n], fy = fys[n];
            __half2 wltH = __float2half2_rn((1.f - fx) * (1.f - fy));
            __half2 wrbH = __float2half2_rn(fx * fy);
            __half2 wlbH = __float2half2_rn((1.f - fx) * fy);       // corner raw+1
            __half2 wrtH = __float2half2_rn(fx * (1.f - fy));       // corner raw+128
            int i0 = min(max(raw, 0), HWD - 1);
            int i1 = min(max(raw + 1, 0), HWD - 1);
            int i2 = min(max(raw + 128, 0), HWD - 1);
            int i3 = min(max(raw + 129, 0), HWD - 1);
            uint4 v0 = *(const uint4*)(xHb + (size_t)i0 * CC + l * 8);
            uint4 v1 = *(const uint4*)(xHb + (size_t)i1 * CC + l * 8);
            uint4 v2 = *(const uint4*)(xHb + (size_t)i2 * CC + l * 8);
            uint4 v3 = *(const uint4*)(xHb + (size_t)i3 * CC + l * 8);
            const __half2* h0 = (const __half2*)&v0;
            const __half2* h1 = (const __half2*)&v1;
            const __half2* h2 = (const __half2*)&v2;
            const __half2* h3 = (const __half2*)&v3;
#pragma unroll
            for (int k = 0; k < 4; k++) {
                __half2 hv = __hmul2(h0[k], wltH);
                hv = __hfma2(h1[k], wlbH, hv);
                hv = __hfma2(h2[k], wrtH, hv);
                hv = __hfma2(h3[k], wrbH, hv);
                float2 f = __half22float2(hv);
                acc[2 * k + 0] += f.x;
                acc[2 * k + 1] += f.y;
            }
        }
        // two aligned float4 stores (pitch 68 keeps 16B alignment)
        float4* xo = (float4*)&xoff[p * 68 + l * 8];
        xo[0] = make_float4(acc[0] * inv9, acc[1] * inv9, acc[2] * inv9, acc[3] * inv9);
        xo[1] = make_float4(acc[4] * inv9, acc[5] * inv9, acc[6] * inv9, acc[7] * inv9);
    }
    __syncthreads();

    // Phase B: y[p][o] = sum_c xoff[p][c] * Wc[o][c], 8 outs/thread.
    // Wc reads are warp-uniform (broadcast); xoff float4 conflict-free.
    int p2 = tid & 31;
    int obase = (tid >> 5) * 8;
    float acc2[8];
#pragma unroll
    for (int q = 0; q < 8; q++) acc2[q] = 0.f;
    for (int c4 = 0; c4 < 64; c4 += 4) {
        float4 xv = *(const float4*)&xoff[p2 * 68 + c4];
#pragma unroll
        for (int q = 0; q < 8; q++) {
            float4 wv = *(const float4*)&Wc_sh[(obase + q) * 64 + c4];  // broadcast
            acc2[q] = fmaf(xv.x, wv.x, acc2[q]);
            acc2[q] = fmaf(xv.y, wv.y, acc2[q]);
            acc2[q] = fmaf(xv.z, wv.z, acc2[q]);
            acc2[q] = fmaf(xv.w, wv.w, acc2[q]);
        }
    }
    __half* yb = g_yH + ((size_t)(s * BB + b) * CC) * HWD + h * WW + w0;
#pragma unroll
    for (int q = 0; q < 8; q++)
        yb[(size_t)(obase + q) * HWD + p2] = __float2half_rn(acc2[q]);

    // BN partial stats from fp32 values: warp over 32 pixels
    int lane = tid & 31;
#pragma unroll
    for (int q = 0; q < 8; q++) {
        float v = acc2[q], v2 = v * v;
#pragma unroll
        for (int ofs = 16; ofs > 0; ofs >>= 1) {
            v += __shfl_down_sync(0xffffffffu, v, ofs);
            v2 += __shfl_down_sync(0xffffffffu, v2, ofs);
        }
        if (lane == 0) {
            atomicAdd(&g_sum[s * CC + obase + q], v);
            atomicAdd(&g_sumsq[s * CC + obase + q], v2);
        }
    }
}

// ---------------- k4: finalize BN coefficients ------------------------------
__global__ void k_stats(const float* __restrict__ gamma, const float* __restrict__ beta) {
    int t = threadIdx.x;
    if (t < NS * CC) {
        float inv = 1.f / CNT;
        float mu = g_sum[t] * inv;
        float var = g_sumsq[t] * inv - mu * mu;
        float A = gamma[t] * rsqrtf(var + BN_EPS);
        g_AB[t * 2] = A;
        g_AB[t * 2 + 1] = beta[t] - mu * A;
    }
}

// ---------------- k5: normalize + SiLU + average scales ---------------------
__global__ void k_final(float* __restrict__ out) {
    int idx = blockIdx.x * blockDim.x + threadIdx.x;   // over B*C*HWD
    int o = (idx >> 14) & 63;
    float r = 0.f;
#pragma unroll
    for (int s = 0; s < NS; s++) {
        float v = __half2float(g_yH[(size_t)s * BB * CC * HWD + idx]);
        int t = s * CC + o;
        float yn = fmaf(v, g_AB[t * 2], g_AB[t * 2 + 1]);
        r += yn / (1.f + expf(-yn));
    }
    out[idx] = r * (1.f / 3.f);
}

// ---------------- launch ----------------------------------------------------
extern "C" void kernel_launch(void* const* d_in, const int* in_sizes, int n_in,
                              void* d_out, int out_size) {
    const float* x     = (const float*)d_in[0];
    const float* Wp    = (const float*)d_in[1];
    const float* bp    = (const float*)d_in[2];
    const float* Wc    = (const float*)d_in[3];
    const float* gamma = (const float*)d_in[4];
    const float* beta  = (const float*)d_in[5];
    float* out = (float*)d_out;

    dim3 tb(32, 8);
    dim3 tg(HWD / 32, CC / 32, BB);
    k_transpose<<<tg, tb>>>(x);
    k_prep<<<((CC * 9 * WSP) + 255) / 256, 256>>>(Wp);
    k_conv<<<dim3(HH, BB), 128>>>(x, bp);
    k_gather<<<dim3(HH * 4, BB, NS), 256>>>(Wc);
    k_stats<<<1, 256>>>(gamma, beta);
    k_final<<<(BB * CC * HWD) / 256, 256>>>(out);
}

// round 13
// speedup vs baseline: 1.2342x; 1.0022x over previous
#include <cuda_runtime.h>
#include <cuda_fp16.h>
#include <cstdint>
#include <math.h>

#define BB 8
#define CC 64
#define HH 128
#define WW 128
#define HWD 16384
#define NS 3
#define K54 54
#define WSP2 20                     // per-scale weight pitch (floats) per tap
#define CNT 131072.0f
#define BN_EPS 1e-5f

// ---------------- scratch (device globals; no runtime allocation) ----------
__device__ __half g_xH[BB * HWD * CC];         // x as [b][hw][c] fp16 (16.8 MB)
__device__ float g_off[BB * HWD * K54];        // offsets channel-last (28.3 MB)
__device__ float g_Wt[NS * CC * 9 * WSP2];     // Wp as [s][ci][tap][18 pad 20]
__device__ __half g_yH[NS * BB * CC * HWD];    // pre-BN y fp16 [s][b][o][hw] (50 MB)
__device__ float g_sum[NS * CC];
__device__ float g_sumsq[NS * CC];
__device__ float g_AB[NS * CC * 2];            // A = gamma*rsqrt(var+eps), B = beta-mu*A

// ---------------- cp.async helpers -----------------------------------------
__device__ __forceinline__ void cpa4(unsigned s, const void* g, bool v) {
    asm volatile("cp.async.ca.shared.global [%0], [%1], 4, %2;"
                 :: "r"(s), "l"(g), "r"(v ? 4u : 0u));
}
__device__ __forceinline__ void cpa16(unsigned s, const void* g) {
    asm volatile("cp.async.cg.shared.global [%0], [%1], 16;" :: "r"(s), "l"(g));
}
__device__ __forceinline__ void cpa_commit() {
    asm volatile("cp.async.commit_group;");
}
template <int N>
__device__ __forceinline__ void cpa_wait() {
    asm volatile("cp.async.wait_group %0;" :: "n"(N));
}

// ---------------- k0: transpose x (b,c,hw) -> (b,hw,c) fp16 ----------------
__global__ void k_transpose(const float* __restrict__ x) {
    __shared__ float t[32][33];                // t[c_local][hw_local]
    int b = blockIdx.z;
    int hw0 = blockIdx.x * 32;
    int c0 = blockIdx.y * 32;
    int tx = threadIdx.x, ty = threadIdx.y;   // (32, 8)
    int tid = ty * 32 + tx;
#pragma unroll
    for (int j = 0; j < 4; j++)
        t[ty + 8 * j][tx] = x[(b * CC + c0 + ty + 8 * j) * HWD + hw0 + tx];
    __syncthreads();
    __half2* outp = (__half2*)g_xH;
#pragma unroll
    for (int idx = tid; idx < 512; idx += 256) {
        int hwl = idx >> 4, cp = idx & 15;
        __half2 v = __floats2half2_rn(t[2 * cp][hwl], t[2 * cp + 1][hwl]);
        outp[((size_t)(b * HWD + hw0 + hwl) * CC + c0) / 2 + cp] = v;
    }
}

// ---------------- k1: transpose Wp (per-scale, padded) + zero stats ---------
__global__ void k_prep(const float* __restrict__ Wp) {
    int idx = blockIdx.x * blockDim.x + threadIdx.x;
    if (idx < NS * CC * 9 * WSP2) {
        int s = idx / (CC * 9 * WSP2);
        int r = idx % (CC * 9 * WSP2);
        int ci = r / (9 * WSP2);
        int r2 = r % (9 * WSP2);
        int tap = r2 / WSP2;
        int k = r2 % WSP2;
        g_Wt[idx] = (k < 18) ? Wp[((s * 18 + k) * CC + ci) * 9 + tap] : 0.f;
    }
    if (idx < NS * CC) { g_sum[idx] = 0.f; g_sumsq[idx] = 0.f; }
}

// ---------------- k2: per-scale 3x3 offset conv, cp.async double-buffered ---
// block = 128 threads = one output row; 18 accumulators (one scale).
__global__ void __launch_bounds__(128) k_conv(const float* __restrict__ x,
                                              const float* __restrict__ bp,
                                              int s) {
    __shared__ float xs[2][3 * 132];   // rows h-1..h+1, padded cols
    __shared__ float ws[2][9 * WSP2];  // [tap][18 pad 20]
    int b = blockIdx.y;
    int h = blockIdx.x;
    int w = threadIdx.x;

    unsigned xs_s[2], ws_s[2];
    xs_s[0] = (unsigned)__cvta_generic_to_shared(&xs[0][0]);
    xs_s[1] = (unsigned)__cvta_generic_to_shared(&xs[1][0]);
    ws_s[0] = (unsigned)__cvta_generic_to_shared(&ws[0][0]);
    ws_s[1] = (unsigned)__cvta_generic_to_shared(&ws[1][0]);

    const float* xb = x + (size_t)b * CC * HWD;
    const float* wt = g_Wt + (size_t)s * CC * 9 * WSP2;

    auto prefetch = [&](int ci, int bi) {
        const float* xc = xb + (size_t)ci * HWD;
#pragma unroll
        for (int it = 0; it < 4; it++) {
            int idx = w + it * 128;
            if (idx < 396) {
                int r = idx / 132, cw = idx % 132 - 1;
                int hh = h - 1 + r;
                bool valid = (hh >= 0) & (hh < HH) & (cw >= 0) & (cw < WW);
                const float* gp = xc + min(max(hh, 0), HH - 1) * WW + min(max(cw, 0), WW - 1);
                cpa4(xs_s[bi] + idx * 4, gp, valid);
            }
        }
        if (w < 45)
            cpa16(ws_s[bi] + w * 16, wt + (size_t)ci * 9 * WSP2 + w * 4);
    };

    float acc[18];
#pragma unroll
    for (int k = 0; k < 18; k++) acc[k] = 0.f;

    prefetch(0, 0);
    cpa_commit();

    for (int ci = 0; ci < CC; ci++) {
        int bi = ci & 1;
        __syncthreads();
        if (ci + 1 < CC) {
            prefetch(ci + 1, bi ^ 1);
            cpa_commit();
            cpa_wait<1>();
        } else {
            cpa_wait<0>();
        }
        __syncthreads();

        float xv[9];
#pragma unroll
        for (int dh = 0; dh < 3; dh++)
#pragma unroll
            for (int dw = 0; dw < 3; dw++)
                xv[dh * 3 + dw] = xs[bi][dh * 132 + w + dw];
#pragma unroll
        for (int tap = 0; tap < 9; tap++) {
            float a = xv[tap];
            const float4* wr = (const float4*)&ws[bi][tap * WSP2];
#pragma unroll
            for (int k4 = 0; k4 < 4; k4++) {
                float4 wv = wr[k4];
                int k = k4 * 4;
                acc[k + 0] = fmaf(a, wv.x, acc[k + 0]);
                acc[k + 1] = fmaf(a, wv.y, acc[k + 1]);
                acc[k + 2] = fmaf(a, wv.z, acc[k + 2]);
                acc[k + 3] = fmaf(a, wv.w, acc[k + 3]);
            }
            acc[16] = fmaf(a, ws[bi][tap * WSP2 + 16], acc[16]);
            acc[17] = fmaf(a, ws[bi][tap * WSP2 + 17], acc[17]);
        }
    }
    float scale = (float)(s + 1);
    float* op = g_off + ((size_t)b * HWD + h * WW + w) * K54 + s * 18;
#pragma unroll
    for (int k = 0; k < 18; k++)
        op[k] = (acc[k] + bp[s * 18 + k]) * scale;
}

// ---------------- k3: gather + HFMA2 bilinear + GEMM + stats (one scale) ----
__global__ void __launch_bounds__(256, 3) k_gather(const float* __restrict__ WcG,
                                                   int s) {
    __shared__ float Wc_sh[64 * 64];      // [o][c]  (straight copy)
    __shared__ float xoff[32 * 68];       // [p][c] pitch 68
    __shared__ float off_sh[32 * 19];     // [p][18] pitch 19

    int h = blockIdx.x >> 2;
    int w0 = (blockIdx.x & 3) * 32;
    int b = blockIdx.y;
    int tid = threadIdx.x;

    {
        const float4* src = (const float4*)(WcG + s * 4096);
        float4* dst = (float4*)Wc_sh;
        for (int idx = tid; idx < 1024; idx += 256) dst[idx] = src[idx];
    }
    {
        const float* ob = g_off + ((size_t)(b * HWD + h * WW + w0)) * K54 + s * 18;
        for (int idx = tid; idx < 32 * 18; idx += 256) {
            int p = idx / 18, j = idx % 18;
            off_sh[p * 19 + j] = ob[p * K54 + j];
        }
    }
    __syncthreads();

    const __half* xHb = g_xH + (size_t)b * HWD * CC;
    const float inv9 = 1.f / 9.f;
    {
        int p = tid >> 3;                  // 0..31
        int l = tid & 7;                   // channel octet
        const float* offp = &off_sh[p * 19];

        int raws[9]; float fxs[9], fys[9];
#pragma unroll
        for (int n = 0; n < 9; n++) {
            float px = (float)(h + n / 3) + offp[n];
            float py = (float)(w0 + p + n % 3) + offp[9 + n];
            float flx = floorf(px), fly = floorf(py);
            fxs[n] = px - flx; fys[n] = py - fly;
            raws[n] = (int)(flx * 128.f + fly);
        }

        float acc[8];
#pragma unroll
        for (int j = 0; j < 8; j++) acc[j] = 0.f;
#pragma unroll
        for (int n = 0; n < 9; n++) {
            int raw = raws[n];
            float fx = fxs[n], fy = fys[n];
            __half2 wltH = __float2half2_rn((1.f - fx) * (1.f - fy));
            __half2 wrbH = __float2half2_rn(fx * fy);
            __half2 wlbH = __float2half2_rn((1.f - fx) * fy);       // corner raw+1
            __half2 wrtH = __float2half2_rn(fx * (1.f - fy));       // corner raw+128
            int i0 = min(max(raw, 0), HWD - 1);
            int i1 = min(max(raw + 1, 0), HWD - 1);
            int i2 = min(max(raw + 128, 0), HWD - 1);
            int i3 = min(max(raw + 129, 0), HWD - 1);
            uint4 v0 = *(const uint4*)(xHb + (size_t)i0 * CC + l * 8);
            uint4 v1 = *(const uint4*)(xHb + (size_t)i1 * CC + l * 8);
            uint4 v2 = *(const uint4*)(xHb + (size_t)i2 * CC + l * 8);
            uint4 v3 = *(const uint4*)(xHb + (size_t)i3 * CC + l * 8);
            const __half2* h0 = (const __half2*)&v0;
            const __half2* h1 = (const __half2*)&v1;
            const __half2* h2 = (const __half2*)&v2;
            const __half2* h3 = (const __half2*)&v3;
#pragma unroll
            for (int k = 0; k < 4; k++) {
                __half2 hv = __hmul2(h0[k], wltH);
                hv = __hfma2(h1[k], wlbH, hv);
                hv = __hfma2(h2[k], wrtH, hv);
                hv = __hfma2(h3[k], wrbH, hv);
                float2 f = __half22float2(hv);
                acc[2 * k + 0] += f.x;
                acc[2 * k + 1] += f.y;
            }
        }
        float4* xo = (float4*)&xoff[p * 68 + l * 8];
        xo[0] = make_float4(acc[0] * inv9, acc[1] * inv9, acc[2] * inv9, acc[3] * inv9);
        xo[1] = make_float4(acc[4] * inv9, acc[5] * inv9, acc[6] * inv9, acc[7] * inv9);
    }
    __syncthreads();

    // Phase B: y[p][o] = sum_c xoff[p][c] * Wc[o][c], 8 outs/thread.
    int p2 = tid & 31;
    int obase = (tid >> 5) * 8;
    float acc2[8];
#pragma unroll
    for (int q = 0; q < 8; q++) acc2[q] = 0.f;
    for (int c4 = 0; c4 < 64; c4 += 4) {
        float4 xv = *(const float4*)&xoff[p2 * 68 + c4];
#pragma unroll
        for (int q = 0; q < 8; q++) {
            float4 wv = *(const float4*)&Wc_sh[(obase + q) * 64 + c4];  // broadcast
            acc2[q] = fmaf(xv.x, wv.x, acc2[q]);
            acc2[q] = fmaf(xv.y, wv.y, acc2[q]);
            acc2[q] = fmaf(xv.z, wv.z, acc2[q]);
            acc2[q] = fmaf(xv.w, wv.w, acc2[q]);
        }
    }
    __half* yb = g_yH + ((size_t)(s * BB + b) * CC) * HWD + h * WW + w0;
#pragma unroll
    for (int q = 0; q < 8; q++)
        yb[(size_t)(obase + q) * HWD + p2] = __float2half_rn(acc2[q]);

    // BN partial stats from fp32 values: warp over 32 pixels
    int lane = tid & 31;
#pragma unroll
    for (int q = 0; q < 8; q++) {
        float v = acc2[q], v2 = v * v;
#pragma unroll
        for (int ofs = 16; ofs > 0; ofs >>= 1) {
            v += __shfl_down_sync(0xffffffffu, v, ofs);
            v2 += __shfl_down_sync(0xffffffffu, v2, ofs);
        }
        if (lane == 0) {
            atomicAdd(&g_sum[s * CC + obase + q], v);
            atomicAdd(&g_sumsq[s * CC + obase + q], v2);
        }
    }
}

// ---------------- k4: finalize BN coefficients ------------------------------
__global__ void k_stats(const float* __restrict__ gamma, const float* __restrict__ beta) {
    int t = threadIdx.x;
    if (t < NS * CC) {
        float inv = 1.f / CNT;
        float mu = g_sum[t] * inv;
        float var = g_sumsq[t] * inv - mu * mu;
        float A = gamma[t] * rsqrtf(var + BN_EPS);
        g_AB[t * 2] = A;
        g_AB[t * 2 + 1] = beta[t] - mu * A;
    }
}

// ---------------- k5: normalize + SiLU + average scales ---------------------
__global__ void k_final(float* __restrict__ out) {
    int idx = blockIdx.x * blockDim.x + threadIdx.x;   // over B*C*HWD
    int o = (idx >> 14) & 63;
    float r = 0.f;
#pragma unroll
    for (int s = 0; s < NS; s++) {
        float v = __half2float(g_yH[(size_t)s * BB * CC * HWD + idx]);
        int t = s * CC + o;
        float yn = fmaf(v, g_AB[t * 2], g_AB[t * 2 + 1]);
        r += yn / (1.f + expf(-yn));
    }
    out[idx] = r * (1.f / 3.f);
}

// ---------------- launch: two-stream pipeline -------------------------------
// default: prep, transpose, conv0, gather0, gather1, gather2, stats, final
// side   : (after conv0) conv1, conv2  — hidden under gather0/gather1
extern "C" void kernel_launch(void* const* d_in, const int* in_sizes, int n_in,
                              void* d_out, int out_size) {
    const float* x     = (const float*)d_in[0];
    const float* Wp    = (const float*)d_in[1];
    const float* bp    = (const float*)d_in[2];
    const float* Wc    = (const float*)d_in[3];
    const float* gamma = (const float*)d_in[4];
    const float* beta  = (const float*)d_in[5];
    float* out = (float*)d_out;

    static cudaStream_t sc = nullptr;
    static cudaEvent_t ev0, ev1, ev2;
    if (!sc) {
        cudaStreamCreateWithFlags(&sc, cudaStreamNonBlocking);
        cudaEventCreateWithFlags(&ev0, cudaEventDisableTiming);
        cudaEventCreateWithFlags(&ev1, cudaEventDisableTiming);
        cudaEventCreateWithFlags(&ev2, cudaEventDisableTiming);
    }

    dim3 tb(32, 8);
    dim3 tg(HWD / 32, CC / 32, BB);
    dim3 cg(HH, BB);
    dim3 gg(HH * 4, BB);

    k_prep<<<(NS * CC * 9 * WSP2 + 255) / 256, 256>>>(Wp);
    k_transpose<<<tg, tb>>>(x);
    k_conv<<<cg, 128>>>(x, bp, 0);
    cudaEventRecord(ev0, 0);

    cudaStreamWaitEvent(sc, ev0, 0);
    k_conv<<<cg, 128, 0, sc>>>(x, bp, 1);
    cudaEventRecord(ev1, sc);
    k_conv<<<cg, 128, 0, sc>>>(x, bp, 2);
    cudaEventRecord(ev2, sc);

    k_gather<<<gg, 256>>>(Wc, 0);
    cudaStreamWaitEvent(0, ev1, 0);
    k_gather<<<gg, 256>>>(Wc, 1);
    cudaStreamWaitEvent(0, ev2, 0);
    k_gather<<<gg, 256>>>(Wc, 2);

    k_stats<<<1, 256>>>(gamma, beta);
    k_final<<<(BB * CC * HWD) / 256, 256>>>(out);
}

// round 14
// speedup vs baseline: 1.3464x; 1.0909x over previous
#include <cuda_runtime.h>
#include <cuda_fp16.h>
#include <cstdint>
#include <math.h>

#define BB 8
#define CC 64
#define HH 128
#define WW 128
#define HWD 16384
#define NS 3
#define K54 54
#define WSP2 20                     // per-scale weight pitch (floats) per tap
#define XSP 136                     // conv xs row pitch (floats): [0..2]=pad,3=left halo,4..131=interior,132=right halo
#define CNT 131072.0f
#define BN_EPS 1e-5f

// ---------------- scratch (device globals; no runtime allocation) ----------
__device__ __half g_xH[BB * HWD * CC];         // x as [b][hw][c] fp16 (16.8 MB)
__device__ float g_off[BB * HWD * K54];        // offsets channel-last (28.3 MB)
__device__ float g_Wt[NS * CC * 9 * WSP2];     // Wp as [s][ci][tap][18 pad 20]
__device__ __half g_yH[NS * BB * CC * HWD];    // pre-BN y fp16 [s][b][o][hw] (50 MB)
__device__ float g_sum[NS * CC];
__device__ float g_sumsq[NS * CC];
__device__ float g_AB[NS * CC * 2];            // A = gamma*rsqrt(var+eps), B = beta-mu*A

// ---------------- cp.async helpers -----------------------------------------
__device__ __forceinline__ void cpa4(unsigned s, const void* g, bool v) {
    asm volatile("cp.async.ca.shared.global [%0], [%1], 4, %2;"
                 :: "r"(s), "l"(g), "r"(v ? 4u : 0u));
}
__device__ __forceinline__ void cpa16(unsigned s, const void* g) {
    asm volatile("cp.async.cg.shared.global [%0], [%1], 16;" :: "r"(s), "l"(g));
}
__device__ __forceinline__ void cpa16p(unsigned s, const void* g, bool v) {
    asm volatile("cp.async.cg.shared.global [%0], [%1], 16, %2;"
                 :: "r"(s), "l"(g), "r"(v ? 16u : 0u));
}
__device__ __forceinline__ void cpa_commit() {
    asm volatile("cp.async.commit_group;");
}
template <int N>
__device__ __forceinline__ void cpa_wait() {
    asm volatile("cp.async.wait_group %0;" :: "n"(N));
}

// ---------------- k0: transpose x (b,c,hw) -> (b,hw,c) fp16 ----------------
__global__ void k_transpose(const float* __restrict__ x) {
    __shared__ float t[32][33];                // t[c_local][hw_local]
    int b = blockIdx.z;
    int hw0 = blockIdx.x * 32;
    int c0 = blockIdx.y * 32;
    int tx = threadIdx.x, ty = threadIdx.y;   // (32, 8)
    int tid = ty * 32 + tx;
#pragma unroll
    for (int j = 0; j < 4; j++)
        t[ty + 8 * j][tx] = x[(b * CC + c0 + ty + 8 * j) * HWD + hw0 + tx];
    __syncthreads();
    __half2* outp = (__half2*)g_xH;
#pragma unroll
    for (int idx = tid; idx < 512; idx += 256) {
        int hwl = idx >> 4, cp = idx & 15;
        __half2 v = __floats2half2_rn(t[2 * cp][hwl], t[2 * cp + 1][hwl]);
        outp[((size_t)(b * HWD + hw0 + hwl) * CC + c0) / 2 + cp] = v;
    }
}

// ---------------- k1: transpose Wp (per-scale, padded) + zero stats ---------
__global__ void k_prep(const float* __restrict__ Wp) {
    int idx = blockIdx.x * blockDim.x + threadIdx.x;
    if (idx < NS * CC * 9 * WSP2) {
        int s = idx / (CC * 9 * WSP2);
        int r = idx % (CC * 9 * WSP2);
        int ci = r / (9 * WSP2);
        int r2 = r % (9 * WSP2);
        int tap = r2 / WSP2;
        int k = r2 % WSP2;
        g_Wt[idx] = (k < 18) ? Wp[((s * 18 + k) * CC + ci) * 9 + tap] : 0.f;
    }
    if (idx < NS * CC) { g_sum[idx] = 0.f; g_sumsq[idx] = 0.f; }
}

// ---------------- k2: per-scale 3x3 conv, 2 rows/block, 16B cp.async --------
// block = 128 threads; rows h0,h0+1; 4 input rows staged (h0-1..h0+2).
// xs row layout: idx 3 = col -1, idx 4+c = col c, idx 132 = col 128.
__global__ void __launch_bounds__(128) k_conv(const float* __restrict__ x,
                                              const float* __restrict__ bp,
                                              int s) {
    __shared__ float xs[2][4 * XSP];   // double-buffered 4 rows
    __shared__ float ws[2][9 * WSP2];  // [tap][18 pad 20]
    int b = blockIdx.y;
    int h0 = blockIdx.x * 2;
    int w = threadIdx.x;

    unsigned xs_s[2], ws_s[2];
    xs_s[0] = (unsigned)__cvta_generic_to_shared(&xs[0][0]);
    xs_s[1] = (unsigned)__cvta_generic_to_shared(&xs[1][0]);
    ws_s[0] = (unsigned)__cvta_generic_to_shared(&ws[0][0]);
    ws_s[1] = (unsigned)__cvta_generic_to_shared(&ws[1][0]);

    const float* xb = x + (size_t)b * CC * HWD;
    const float* wt = g_Wt + (size_t)s * CC * 9 * WSP2;

    // 4 rows x 34 tasks: j<32 -> 16B interior chunk, j=32 -> left halo, j=33 -> right halo
    auto prefetch = [&](int ci, int bi) {
        const float* xc = xb + (size_t)ci * HWD;
#pragma unroll
        for (int it = 0; it < 2; it++) {
            int task = w + it * 128;
            if (task < 136) {
                int r = task / 34, j = task % 34;
                int hh = h0 - 1 + r;
                bool rok = (hh >= 0) & (hh < HH);
                const float* rowp = xc + min(max(hh, 0), HH - 1) * WW;
                unsigned rowd = xs_s[bi] + (unsigned)(r * XSP * 4);
                if (j < 32) {
                    cpa16p(rowd + 16 + j * 16, rowp + j * 4, rok);
                } else if (j == 32) {
                    cpa4(rowd + 12, rowp - 1, rok);            // col -1 (never valid at w=0 row edge handled by rok only... col-1 invalid always at left edge)
                } else {
                    cpa4(rowd + 528, rowp + 128, false);       // col 128 is out of row: always zero
                }
            }
        }
        if (w < 45)
            cpa16(ws_s[bi] + w * 16, wt + (size_t)ci * 9 * WSP2 + w * 4);
    };
    // note: left halo col -1 is out of bounds horizontally -> must be zero too
    // (handled below by overriding valid=false for j==32)

    float acc0[18], acc1[18];
#pragma unroll
    for (int k = 0; k < 18; k++) { acc0[k] = 0.f; acc1[k] = 0.f; }

    // fix halo validity: redo lambda inline (j==32 must be zero: col -1 < 0)
    auto prefetch2 = [&](int ci, int bi) {
        const float* xc = xb + (size_t)ci * HWD;
#pragma unroll
        for (int it = 0; it < 2; it++) {
            int task = w + it * 128;
            if (task < 136) {
                int r = task / 34, j = task % 34;
                int hh = h0 - 1 + r;
                bool rok = (hh >= 0) & (hh < HH);
                const float* rowp = xc + min(max(hh, 0), HH - 1) * WW;
                unsigned rowd = xs_s[bi] + (unsigned)(r * XSP * 4);
                if (j < 32) cpa16p(rowd + 16 + j * 16, rowp + j * 4, rok);
                else if (j == 32) cpa4(rowd + 12, rowp, false);       // col -1 -> 0
                else cpa4(rowd + 528, rowp, false);                   // col 128 -> 0
            }
        }
        if (w < 45)
            cpa16(ws_s[bi] + w * 16, wt + (size_t)ci * 9 * WSP2 + w * 4);
    };
    (void)prefetch;

    prefetch2(0, 0);
    cpa_commit();

    for (int ci = 0; ci < CC; ci++) {
        int bi = ci & 1;
        __syncthreads();
        if (ci + 1 < CC) {
            prefetch2(ci + 1, bi ^ 1);
            cpa_commit();
            cpa_wait<1>();
        } else {
            cpa_wait<0>();
        }
        __syncthreads();

        float xv0[9], xv1[9];
#pragma unroll
        for (int dh = 0; dh < 3; dh++)
#pragma unroll
            for (int dw = 0; dw < 3; dw++) {
                xv0[dh * 3 + dw] = xs[bi][dh * XSP + 3 + w + dw];
                xv1[dh * 3 + dw] = xs[bi][(dh + 1) * XSP + 3 + w + dw];
            }
#pragma unroll
        for (int tap = 0; tap < 9; tap++) {
            float a0 = xv0[tap], a1 = xv1[tap];
            const float4* wr = (const float4*)&ws[bi][tap * WSP2];
#pragma unroll
            for (int k4 = 0; k4 < 4; k4++) {
                float4 wv = wr[k4];
                int k = k4 * 4;
                acc0[k + 0] = fmaf(a0, wv.x, acc0[k + 0]);
                acc1[k + 0] = fmaf(a1, wv.x, acc1[k + 0]);
                acc0[k + 1] = fmaf(a0, wv.y, acc0[k + 1]);
                acc1[k + 1] = fmaf(a1, wv.y, acc1[k + 1]);
                acc0[k + 2] = fmaf(a0, wv.z, acc0[k + 2]);
                acc1[k + 2] = fmaf(a1, wv.z, acc1[k + 2]);
                acc0[k + 3] = fmaf(a0, wv.w, acc0[k + 3]);
                acc1[k + 3] = fmaf(a1, wv.w, acc1[k + 3]);
            }
            float w16 = ws[bi][tap * WSP2 + 16], w17 = ws[bi][tap * WSP2 + 17];
            acc0[16] = fmaf(a0, w16, acc0[16]);
            acc1[16] = fmaf(a1, w16, acc1[16]);
            acc0[17] = fmaf(a0, w17, acc0[17]);
            acc1[17] = fmaf(a1, w17, acc1[17]);
        }
    }
    float scale = (float)(s + 1);
    float* op0 = g_off + ((size_t)b * HWD + h0 * WW + w) * K54 + s * 18;
    float* op1 = op0 + (size_t)WW * K54;
#pragma unroll
    for (int k = 0; k < 18; k++) {
        float bk = bp[s * 18 + k];
        op0[k] = (acc0[k] + bk) * scale;
        op1[k] = (acc1[k] + bk) * scale;
    }
}

// ---------------- k3: gather + HFMA2 bilinear + GEMM + stats (one scale) ----
__global__ void __launch_bounds__(256, 3) k_gather(const float* __restrict__ WcG,
                                                   int s) {
    __shared__ float Wc_sh[64 * 64];      // [o][c]  (straight copy)
    __shared__ float xoff[32 * 68];       // [p][c] pitch 68
    __shared__ float off_sh[32 * 19];     // [p][18] pitch 19

    int h = blockIdx.x >> 2;
    int w0 = (blockIdx.x & 3) * 32;
    int b = blockIdx.y;
    int tid = threadIdx.x;

    {
        const float4* src = (const float4*)(WcG + s * 4096);
        float4* dst = (float4*)Wc_sh;
        for (int idx = tid; idx < 1024; idx += 256) dst[idx] = src[idx];
    }
    {
        const float* ob = g_off + ((size_t)(b * HWD + h * WW + w0)) * K54 + s * 18;
        for (int idx = tid; idx < 32 * 18; idx += 256) {
            int p = idx / 18, j = idx % 18;
            off_sh[p * 19 + j] = ob[p * K54 + j];
        }
    }
    __syncthreads();

    const __half* xHb = g_xH + (size_t)b * HWD * CC;
    const float inv9 = 1.f / 9.f;
    {
        int p = tid >> 3;                  // 0..31
        int l = tid & 7;                   // channel octet
        const float* offp = &off_sh[p * 19];

        int raws[9]; float fxs[9], fys[9];
#pragma unroll
        for (int n = 0; n < 9; n++) {
            float px = (float)(h + n / 3) + offp[n];
            float py = (float)(w0 + p + n % 3) + offp[9 + n];
            float flx = floorf(px), fly = floorf(py);
            fxs[n] = px - flx; fys[n] = py - fly;
            raws[n] = (int)(flx * 128.f + fly);
        }

        float acc[8];
#pragma unroll
        for (int j = 0; j < 8; j++) acc[j] = 0.f;
#pragma unroll
        for (int n = 0; n < 9; n++) {
            int raw = raws[n];
            float fx = fxs[n], fy = fys[n];
            __half2 wltH = __float2half2_rn((1.f - fx) * (1.f - fy));
            __half2 wrbH = __float2half2_rn(fx * fy);
            __half2 wlbH = __float2half2_rn((1.f - fx) * fy);
            __half2 wrtH = __float2half2_rn(fx * (1.f - fy));
            int i0 = min(max(raw, 0), HWD - 1);
            int i1 = min(max(raw + 1, 0), HWD - 1);
            int i2 = min(max(raw + 128, 0), HWD - 1);
            int i3 = min(max(raw + 129, 0), HWD - 1);
            uint4 v0 = *(const uint4*)(xHb + (size_t)i0 * CC + l * 8);
            uint4 v1 = *(const uint4*)(xHb + (size_t)i1 * CC + l * 8);
            uint4 v2 = *(const uint4*)(xHb + (size_t)i2 * CC + l * 8);
            uint4 v3 = *(const uint4*)(xHb + (size_t)i3 * CC + l * 8);
            const __half2* h0 = (const __half2*)&v0;
            const __half2* h1 = (const __half2*)&v1;
            const __half2* h2 = (const __half2*)&v2;
            const __half2* h3 = (const __half2*)&v3;
#pragma unroll
            for (int k = 0; k < 4; k++) {
                __half2 hv = __hmul2(h0[k], wltH);
                hv = __hfma2(h1[k], wlbH, hv);
                hv = __hfma2(h2[k], wrtH, hv);
                hv = __hfma2(h3[k], wrbH, hv);
                float2 f = __half22float2(hv);
                acc[2 * k + 0] += f.x;
                acc[2 * k + 1] += f.y;
            }
        }
        float4* xo = (float4*)&xoff[p * 68 + l * 8];
        xo[0] = make_float4(acc[0] * inv9, acc[1] * inv9, acc[2] * inv9, acc[3] * inv9);
        xo[1] = make_float4(acc[4] * inv9, acc[5] * inv9, acc[6] * inv9, acc[7] * inv9);
    }
    __syncthreads();

    int p2 = tid & 31;
    int obase = (tid >> 5) * 8;
    float acc2[8];
#pragma unroll
    for (int q = 0; q < 8; q++) acc2[q] = 0.f;
    for (int c4 = 0; c4 < 64; c4 += 4) {
        float4 xv = *(const float4*)&xoff[p2 * 68 + c4];
#pragma unroll
        for (int q = 0; q < 8; q++) {
            float4 wv = *(const float4*)&Wc_sh[(obase + q) * 64 + c4];  // broadcast
            acc2[q] = fmaf(xv.x, wv.x, acc2[q]);
            acc2[q] = fmaf(xv.y, wv.y, acc2[q]);
            acc2[q] = fmaf(xv.z, wv.z, acc2[q]);
            acc2[q] = fmaf(xv.w, wv.w, acc2[q]);
        }
    }
    __half* yb = g_yH + ((size_t)(s * BB + b) * CC) * HWD + h * WW + w0;
#pragma unroll
    for (int q = 0; q < 8; q++)
        yb[(size_t)(obase + q) * HWD + p2] = __float2half_rn(acc2[q]);

    int lane = tid & 31;
#pragma unroll
    for (int q = 0; q < 8; q++) {
        float v = acc2[q], v2 = v * v;
#pragma unroll
        for (int ofs = 16; ofs > 0; ofs >>= 1) {
            v += __shfl_down_sync(0xffffffffu, v, ofs);
            v2 += __shfl_down_sync(0xffffffffu, v2, ofs);
        }
        if (lane == 0) {
            atomicAdd(&g_sum[s * CC + obase + q], v);
            atomicAdd(&g_sumsq[s * CC + obase + q], v2);
        }
    }
}

// ---------------- k4: finalize BN coefficients ------------------------------
__global__ void k_stats(const float* __restrict__ gamma, const float* __restrict__ beta) {
    int t = threadIdx.x;
    if (t < NS * CC) {
        float inv = 1.f / CNT;
        float mu = g_sum[t] * inv;
        float var = g_sumsq[t] * inv - mu * mu;
        float A = gamma[t] * rsqrtf(var + BN_EPS);
        g_AB[t * 2] = A;
        g_AB[t * 2 + 1] = beta[t] - mu * A;
    }
}

// ---------------- k5: normalize + SiLU + average scales ---------------------
__global__ void k_final(float* __restrict__ out) {
    int idx = blockIdx.x * blockDim.x + threadIdx.x;   // over B*C*HWD
    int o = (idx >> 14) & 63;
    float r = 0.f;
#pragma unroll
    for (int s = 0; s < NS; s++) {
        float v = __half2float(g_yH[(size_t)s * BB * CC * HWD + idx]);
        int t = s * CC + o;
        float yn = fmaf(v, g_AB[t * 2], g_AB[t * 2 + 1]);
        r += yn / (1.f + expf(-yn));
    }
    out[idx] = r * (1.f / 3.f);
}

// ---------------- launch: two-stream pipeline -------------------------------
// main: prep, conv0, gather0, gather1, gather2, stats, final
// side: transpose (|| conv0), then conv1, conv2 (|| gather0/1)
extern "C" void kernel_launch(void* const* d_in, const int* in_sizes, int n_in,
                              void* d_out, int out_size) {
    const float* x     = (const float*)d_in[0];
    const float* Wp    = (const float*)d_in[1];
    const float* bp    = (const float*)d_in[2];
    const float* Wc    = (const float*)d_in[3];
    const float* gamma = (const float*)d_in[4];
    const float* beta  = (const float*)d_in[5];
    float* out = (float*)d_out;

    static cudaStream_t sc = nullptr;
    static cudaEvent_t evP, evT, ev0, ev1, ev2;
    if (!sc) {
        cudaStreamCreateWithFlags(&sc, cudaStreamNonBlocking);
        cudaEventCreateWithFlags(&evP, cudaEventDisableTiming);
        cudaEventCreateWithFlags(&evT, cudaEventDisableTiming);
        cudaEventCreateWithFlags(&ev0, cudaEventDisableTiming);
        cudaEventCreateWithFlags(&ev1, cudaEventDisableTiming);
        cudaEventCreateWithFlags(&ev2, cudaEventDisableTiming);
    }

    dim3 tb(32, 8);
    dim3 tg(HWD / 32, CC / 32, BB);
    dim3 cg(HH / 2, BB);
    dim3 gg(HH * 4, BB);

    k_prep<<<(NS * CC * 9 * WSP2 + 255) / 256, 256>>>(Wp);
    cudaEventRecord(evP, 0);

    // side: transpose runs concurrent with conv0; convs 1,2 after conv0 done
    cudaStreamWaitEvent(sc, evP, 0);
    k_transpose<<<tg, tb, 0, sc>>>(x);
    cudaEventRecord(evT, sc);

    k_conv<<<cg, 128>>>(x, bp, 0);
    cudaEventRecord(ev0, 0);

    cudaStreamWaitEvent(sc, ev0, 0);
    k_conv<<<cg, 128, 0, sc>>>(x, bp, 1);
    cudaEventRecord(ev1, sc);
    k_conv<<<cg, 128, 0, sc>>>(x, bp, 2);
    cudaEventRecord(ev2, sc);

    cudaStreamWaitEvent(0, evT, 0);
    k_gather<<<gg, 256>>>(Wc, 0);
    cudaStreamWaitEvent(0, ev1, 0);
    k_gather<<<gg, 256>>>(Wc, 1);
    cudaStreamWaitEvent(0, ev2, 0);
    k_gather<<<gg, 256>>>(Wc, 2);

    k_stats<<<1, 256>>>(gamma, beta);
    k_final<<<(BB * CC * HWD) / 256, 256>>>(out);
}